// round 9
// baseline (speedup 1.0000x reference)
#include <cuda_runtime.h>
#include <cfloat>

#define BB 256
#define TT 512
#define KK 128
#define TRP 132   // padded transposed-transitions row stride (floats)
#define PT  132   // padded partials row stride (floats)

// Scratch (__device__ globals only — no runtime allocation)
__device__ float g_states[(size_t)BB * TT * KK];   // 64 MiB Viterbi states
__device__ int   g_order[BB];                      // bid -> batch

// ---------------------------------------------------------------------------
// Rank batches by descending length; bid r (r<148) and bid 403-r land on the
// same SM under the classic placement: long batches pair with short ones.
// ---------------------------------------------------------------------------
__global__ void order_kernel(const int* __restrict__ lens)
{
    __shared__ int sl[BB];
    const int b = threadIdx.x;
    sl[b] = lens[b];
    __syncthreads();
    const int L = sl[b];
    int r = 0;
    #pragma unroll 8
    for (int i = 0; i < BB; ++i) {
        int Li = sl[i];
        r += (Li > L) || (Li == L && i < b);
    }
    g_order[(r < 148) ? r : (403 - r)] = b;
}

// ---------------------------------------------------------------------------
// Packed f32x2 add (sm_103a). max.f32x2 does not exist; FMNMX stays scalar.
// ---------------------------------------------------------------------------
__device__ __forceinline__ unsigned long long addx2(unsigned long long a,
                                                    unsigned long long b) {
    unsigned long long r;
    asm("add.rn.f32x2 %0, %1, %2;" : "=l"(r) : "l"(a), "l"(b));
    return r;
}
__device__ __forceinline__ float2 unpk(unsigned long long v) {
    float2 r;
    asm("mov.b64 {%0, %1}, %2;" : "=f"(r.x), "=f"(r.y) : "l"(v));
    return r;
}
__device__ __forceinline__ unsigned long long pk(float lo, float hi) {
    unsigned long long r;
    asm("mov.b64 %0, {%1, %2};" : "=l"(r) : "f"(lo), "f"(hi));
    return r;
}

// ---------------------------------------------------------------------------
// Backtrace helpers (warp-uniform argmax, first-index tie-break)
// ---------------------------------------------------------------------------
__device__ __forceinline__ unsigned redux_max_u32(unsigned v) {
    unsigned r;
    asm("redux.sync.max.u32 %0, %1, 0xffffffff;" : "=r"(r) : "r"(v));
    return r;
}
__device__ __forceinline__ unsigned redux_min_u32(unsigned v) {
    unsigned r;
    asm("redux.sync.min.u32 %0, %1, 0xffffffff;" : "=r"(r) : "r"(v));
    return r;
}
__device__ __forceinline__ unsigned fkey(float f) {
    unsigned u = __float_as_uint(f);
    return u ^ ((unsigned)((int)u >> 31) | 0x80000000u);
}
__device__ __forceinline__ int argmax128(float4 v, int l)
{
    unsigned k0 = fkey(v.x), k1 = fkey(v.y), k2 = fkey(v.z), k3 = fkey(v.w);
    unsigned km = max(max(k0, k1), max(k2, k3));
    unsigned M  = redux_max_u32(km);
    unsigned il = 0xFFFFFFFFu;
    if (k3 == M) il = 4 * l + 3;
    if (k2 == M) il = 4 * l + 2;
    if (k1 == M) il = 4 * l + 1;
    if (k0 == M) il = 4 * l + 0;
    return (int)redux_min_u32(il);
}

__device__ __forceinline__ void bt_step(float4 cur, const float* __restrict__ s_tr,
                                        int& tag, float* __restrict__ outrow,
                                        int l, bool addtr)
{
    if (addtr) {
        float4 tc = *reinterpret_cast<const float4*>(&s_tr[tag * TRP + 4 * l]);
        cur.x += tc.x; cur.y += tc.y; cur.z += tc.z; cur.w += tc.w;
    }
    tag = argmax128(cur, l);
    float4 r;
    r.x = (4 * l + 0 == tag) ? 1.0f : 0.0f;
    r.y = (4 * l + 1 == tag) ? 1.0f : 0.0f;
    r.z = (4 * l + 2 == tag) ? 1.0f : 0.0f;
    r.w = (4 * l + 3 == tag) ? 1.0f : 0.0f;
    reinterpret_cast<float4*>(outrow)[l] = r;
}

// ---------------------------------------------------------------------------
// Fused Viterbi: one CTA = one batch, 128 threads. State lives in REGISTERS
// (thread tid holds S[tid]); warp w reduces its own i-range [32w,32w+32) via
// intra-warp shuffles; only 4 partials/thread cross warps through smem with
// ONE barrier per step. No smem round trip for the state itself.
// ---------------------------------------------------------------------------
__global__ void __launch_bounds__(128, 2) crf_kernel(
    const float* __restrict__ pot,
    const float* __restrict__ trans,
    const int*   __restrict__ lens,
    float*       __restrict__ out)
{
    extern __shared__ float sm[];
    float* s_tr = sm;                  // KK*TRP: transposed transitions
    float* s_pt = sm + KK * TRP;       // 2 * 4*PT ping-pong partials

    const int tid = threadIdx.x;
    const int w   = tid >> 5;          // warp: owns i in [32w, 32w+32)
    const int l   = tid & 31;
    const int b   = g_order[blockIdx.x];
    const int len = lens[b];
    const size_t base = (size_t)b * TT * KK;

    // Stage transposed transitions in smem for the backtrace (coalesced LDG).
    #pragma unroll 4
    for (int i = 0; i < KK; ++i)
        s_tr[tid * TRP + i] = trans[i * KK + tid];

    // Forward transitions in registers: for i = 32w+r, this thread needs
    // T[i][l], T[i][32+l], T[i][64+l], T[i][96+l] (its 4 partial columns),
    // packed as two f32x2 pairs per r.
    unsigned long long tr0[32], tr1[32];
    #pragma unroll
    for (int r = 0; r < 32; ++r) {
        const float* row = trans + (size_t)(32 * w + r) * KK;
        tr0[r] = pk(row[l],      row[32 + l]);
        tr1[r] = pk(row[64 + l], row[96 + l]);
    }

    // State in register: thread tid holds S[tid]. Warp w's lanes hold exactly
    // S[i] for i in its own reduction range.
    float S = pot[base + tid];
    g_states[base + tid] = S;

    // Depth-4 prefetch ring for the emission potentials.
    const int lm1 = len - 1;
    float xr[4];
    #pragma unroll
    for (int d = 0; d < 4; ++d) {
        int tt = (1 + d < lm1) ? (1 + d) : lm1;
        xr[d] = (len > 1) ? pot[base + (size_t)tt * KK + tid] : 0.0f;
    }
    __syncthreads();

    // ---- forward Viterbi ----
    #pragma unroll 2
    for (int t = 1; t < len; ++t) {
        float x = xr[(t - 1) & 3];
        int tn = (t + 4 < lm1) ? (t + 4) : lm1;
        xr[(t - 1) & 3] = pot[base + (size_t)tn * KK + tid];   // prefetch t+4

        // Phase A: intra-warp partials over own i-range, state via shuffles.
        float m0 = -FLT_MAX, m1 = -FLT_MAX, m2 = -FLT_MAX, m3 = -FLT_MAX;
        float n0 = -FLT_MAX, n1 = -FLT_MAX, n2 = -FLT_MAX, n3 = -FLT_MAX;
        #pragma unroll
        for (int r = 0; r < 32; r += 2) {
            float sb0 = __shfl_sync(0xffffffffu, S, r);
            unsigned long long sp0 = pk(sb0, sb0);
            float2 a0 = unpk(addx2(sp0, tr0[r]));
            float2 a1 = unpk(addx2(sp0, tr1[r]));
            m0 = fmaxf(m0, a0.x);
            m1 = fmaxf(m1, a0.y);
            m2 = fmaxf(m2, a1.x);
            m3 = fmaxf(m3, a1.y);
            float sb1 = __shfl_sync(0xffffffffu, S, r + 1);
            unsigned long long sp1 = pk(sb1, sb1);
            float2 a2 = unpk(addx2(sp1, tr0[r + 1]));
            float2 a3 = unpk(addx2(sp1, tr1[r + 1]));
            n0 = fmaxf(n0, a2.x);
            n1 = fmaxf(n1, a2.y);
            n2 = fmaxf(n2, a3.x);
            n3 = fmaxf(n3, a3.y);
        }
        m0 = fmaxf(m0, n0);
        m1 = fmaxf(m1, n1);
        m2 = fmaxf(m2, n2);
        m3 = fmaxf(m3, n3);

        // Phase B: publish partials (ping-pong buffer on t parity).
        float* pb = s_pt + (t & 1) * 4 * PT + w * PT;
        pb[l]      = m0;
        pb[32 + l] = m1;
        pb[64 + l] = m2;
        pb[96 + l] = m3;
        __syncthreads();

        // Phase C: combine 4 warp-partials for own column; S stays in reg.
        const float* pr = s_pt + (t & 1) * 4 * PT;
        float p0 = pr[0 * PT + tid];
        float p1 = pr[1 * PT + tid];
        float p2 = pr[2 * PT + tid];
        float p3 = pr[3 * PT + tid];
        S = x + fmaxf(fmaxf(p0, p1), fmaxf(p2, p3));
        g_states[base + (size_t)t * KK + tid] = S;
    }

    // ---- epilogue: warp 0 backtraces; warps 1-3 write tag-0 rows >= len ----
    if (w != 0) {
        const int total = (TT - len) * 32;
        for (int idx = (w - 1) * 32 + l; idx < total; idx += 96) {
            int r = len + (idx >> 5);
            int c = idx & 31;
            float4 v = make_float4(c == 0 ? 1.0f : 0.0f, 0.0f, 0.0f, 0.0f);
            reinterpret_cast<float4*>(out + base + (size_t)r * KK)[c] = v;
        }
        return;
    }

    auto LDst = [&](int t) -> float4 {
        if (t < 0) return make_float4(0.f, 0.f, 0.f, 0.f);
        return reinterpret_cast<const float4*>(&g_states[base + (size_t)t * KK])[l];
    };
    float* const ob = out + base;

    int tag = 0;
    float4 c0 = LDst(len - 1);
    int t = len - 2;
    float4 p0 = LDst(t), p1 = LDst(t - 1), p2 = LDst(t - 2), p3 = LDst(t - 3);

    bt_step(c0, s_tr, tag, ob + (size_t)(len - 1) * KK, l, false);

    while (t >= 3) {
        bt_step(p0, s_tr, tag, ob + (size_t)(t    ) * KK, l, true);  p0 = LDst(t - 4);
        bt_step(p1, s_tr, tag, ob + (size_t)(t - 1) * KK, l, true);  p1 = LDst(t - 5);
        bt_step(p2, s_tr, tag, ob + (size_t)(t - 2) * KK, l, true);  p2 = LDst(t - 6);
        bt_step(p3, s_tr, tag, ob + (size_t)(t - 3) * KK, l, true);  p3 = LDst(t - 7);
        t -= 4;
    }
    if (t >= 0) bt_step(p0, s_tr, tag, ob + (size_t)(t    ) * KK, l, true);
    if (t >= 1) bt_step(p1, s_tr, tag, ob + (size_t)(t - 1) * KK, l, true);
    if (t >= 2) bt_step(p2, s_tr, tag, ob + (size_t)(t - 2) * KK, l, true);
}

// ---------------------------------------------------------------------------
extern "C" void kernel_launch(void* const* d_in, const int* in_sizes, int n_in,
                              void* d_out, int out_size)
{
    const float* pot   = (const float*)d_in[0];   // (B,T,K) f32
    const float* trans = (const float*)d_in[1];   // (K,K)   f32
    const int*   lens  = (const int*)  d_in[2];   // (B,)    i32
    float* out = (float*)d_out;                   // (B,T,K) f32

    const int smem = (KK * TRP + 2 * 4 * PT) * (int)sizeof(float);  // 71,808 B
    cudaFuncSetAttribute(crf_kernel, cudaFuncAttributeMaxDynamicSharedMemorySize, smem);

    order_kernel<<<1, BB>>>(lens);
    crf_kernel<<<BB, 128, smem>>>(pot, trans, lens, out);
}